// round 2
// baseline (speedup 1.0000x reference)
#include <cuda_runtime.h>
#include <cuda_bf16.h>
#include <cstdint>

// ---------------- problem constants ----------------
#define BB   64
#define CC   768
#define PP   16
#define HH   14
#define HCC  7
#define NFINE 196          // 14*14
#define NCOARSE 49         // 7*7
#define KDIM 768           // 3*16*16
#define N3   2304          // 3*C

// ---------------- device scratch (static, no allocs) ----------------
__device__ float g_patches[BB*NFINE*KDIM];     // fine patch vectors (12544,768)
__device__ float g_pe     [BB*NFINE*CC];       // fine patch embeddings
__device__ float g_cpat   [BB*NCOARSE*KDIM];   // coarse patch vectors (3136,768)
__device__ float g_cpe    [BB*NCOARSE*CC];     // coarse embeddings
__device__ float g_tok    [BB*NCOARSE*4*CC];   // mini-attn tokens (12544,768)
__device__ float g_qkv    [BB*NCOARSE*4*N3];   // qkv (12544,2304)
__device__ float g_o      [BB*NCOARSE*4*CC];   // attn output
__device__ float g_po     [BB*NCOARSE*4*CC];   // proj output
__device__ float g_mean   [BB*NCOARSE*CC];     // mean over 4 tokens
__device__ float g_z      [BB*NCOARSE*CC];     // zero_conv residual
__device__ int   g_m32    [BB*NCOARSE];
__device__ int   g_finepos[BB*NFINE];
__device__ int   g_coarsepos[BB*NCOARSE];
__device__ int   g_seq[BB];
__device__ int   g_cls[BB];
__device__ int   g_total;
__device__ int   g_flag;                        // nonzero if zero_w/zero_b not all-zero

// ---------------- mask / positions / flag ----------------
__global__ void __launch_bounds__(512) mask_kernel(
    const float* __restrict__ e, const float* __restrict__ zw,
    const float* __restrict__ zb, float* __restrict__ out, int out_size)
{
    __shared__ int s_flag;
    __shared__ int s_nc[BB];
    __shared__ int s_cls[BB+1];
    int t = threadIdx.x;
    if (t == 0) s_flag = 0;
    __syncthreads();
    int nz = 0;
    for (int i = t; i < CC*CC; i += blockDim.x) nz |= (zw[i] != 0.0f);
    for (int i = t; i < CC;    i += blockDim.x) nz |= (zb[i] != 0.0f);
    if (nz) atomicOr(&s_flag, 1);

    if (t < BB) {
        int b = t, nc = 0;
        const float* eb = e + b*NFINE;
        for (int cc = 0; cc < NCOARSE; cc++) {
            int ci = cc / 7, cj = cc % 7;
            float m = (eb[(2*ci)*14 + 2*cj]   + eb[(2*ci)*14 + 2*cj+1] +
                       eb[(2*ci+1)*14 + 2*cj] + eb[(2*ci+1)*14 + 2*cj+1]) * 0.25f;
            int sel = m < 0.5f;
            g_m32[b*NCOARSE + cc] = sel;
            nc += sel;
        }
        s_nc[t] = nc;
    }
    __syncthreads();
    if (t == 0) {
        int acc = 0;
        for (int b = 0; b < BB; b++) {
            s_cls[b] = acc;
            g_cls[b] = acc;
            int nc = s_nc[b];
            int seq = 1 + 4*(NCOARSE - nc) + nc;
            g_seq[b] = seq;
            acc += seq;
        }
        g_total = acc;
        s_cls[BB] = acc;
        g_flag = s_flag;
    }
    __syncthreads();
    if (t < BB) {
        int b = t;
        int base = s_cls[b];
        int rank = 0;
        for (int f = 0; f < NFINE; f++) {
            int i = f / 14, j = f % 14;
            int sel = g_m32[b*NCOARSE + (i>>1)*7 + (j>>1)];
            g_finepos[b*NFINE + f] = sel ? -1 : (base + 1 + rank);
            rank += !sel;
        }
        int crank = 0;
        for (int cc = 0; cc < NCOARSE; cc++) {
            int sel = g_m32[b*NCOARSE + cc];
            g_coarsepos[b*NCOARSE + cc] = sel ? (base + 1 + rank + crank) : -1;
            crank += sel;
        }
    }
    __syncthreads();
    // optional tail: seq_lengths + cls_loc appended as floats
    long long total = s_cls[BB];
    long long need = total * CC + 2*BB;
    if ((long long)out_size == need && t < BB) {
        out[total*CC + t]      = (float)g_seq[t];
        out[total*CC + BB + t] = (float)g_cls[t];
    }
}

// ---------------- patch extraction ----------------
__global__ void __launch_bounds__(256) extract_fine(const float* __restrict__ x)
{
    int idx = blockIdx.x * blockDim.x + threadIdx.x;
    if (idx >= BB*NFINE*KDIM) return;
    int row = idx / KDIM;
    int k   = idx - row * KDIM;
    int c  = k >> 8;            // /256
    int pi = (k >> 4) & 15;
    int pj = k & 15;
    int b = row / NFINE;
    int f = row - b * NFINE;
    int i = f / 14, j = f - i*14;
    g_patches[idx] = x[((size_t)(b*3 + c)*224 + i*16 + pi)*224 + j*16 + pj];
}

__global__ void __launch_bounds__(256) extract_coarse(const float* __restrict__ x)
{
    int idx = blockIdx.x * blockDim.x + threadIdx.x;
    if (idx >= BB*NCOARSE*KDIM) return;
    int row = idx / KDIM;
    int k   = idx - row * KDIM;
    int c  = k >> 8;
    int pi = (k >> 4) & 15;
    int pj = k & 15;
    int b  = row / NCOARSE;
    int cc = row - b * NCOARSE;
    int ci = cc / 7, cj = cc - ci*7;
    int y = (ci*16 + pi) * 2;
    int xx = (cj*16 + pj) * 2;
    const float* base = x + ((size_t)(b*3 + c)*224 + y)*224 + xx;
    g_cpat[idx] = (base[0] + base[1] + base[224] + base[225]) * 0.25f;
}

// ---------------- SGEMM: C = A(MxK) @ B(KxN) + bias ----------------
#define BM 128
#define BN 128
#define BK 8
__global__ void __launch_bounds__(256) sgemm_bias(
    const float* __restrict__ A, const float* __restrict__ Bm,
    const float* __restrict__ bias, float* __restrict__ Cm,
    int M, int N, int K, const int* flagptr)
{
    if (flagptr && *flagptr == 0) return;
    __shared__ float As[BK][BM];
    __shared__ float Bs[BK][BN];
    int tid = threadIdx.x;
    int row0 = blockIdx.y * BM;
    int col0 = blockIdx.x * BN;
    int tx = tid & 15;       // 0..15
    int ty = tid >> 4;       // 0..15
    float acc[8][8];
#pragma unroll
    for (int i = 0; i < 8; i++)
#pragma unroll
        for (int j = 0; j < 8; j++) acc[i][j] = 0.0f;

    int aRow = tid >> 1;          // 0..127
    int aCol = (tid & 1) * 4;     // 0 or 4
    int bRow = tid >> 5;          // 0..7
    int bCol = (tid & 31) * 4;    // 0..124

    for (int k0 = 0; k0 < K; k0 += BK) {
        float4 av = make_float4(0.f, 0.f, 0.f, 0.f);
        int gm = row0 + aRow;
        if (gm < M) av = *reinterpret_cast<const float4*>(&A[(size_t)gm*K + k0 + aCol]);
        As[aCol+0][aRow] = av.x;
        As[aCol+1][aRow] = av.y;
        As[aCol+2][aRow] = av.z;
        As[aCol+3][aRow] = av.w;
        float4 bv = *reinterpret_cast<const float4*>(&Bm[(size_t)(k0 + bRow)*N + col0 + bCol]);
        *reinterpret_cast<float4*>(&Bs[bRow][bCol]) = bv;
        __syncthreads();
#pragma unroll
        for (int kk = 0; kk < BK; kk++) {
            float4 a0 = *reinterpret_cast<const float4*>(&As[kk][ty*8]);
            float4 a1 = *reinterpret_cast<const float4*>(&As[kk][ty*8+4]);
            float4 b0 = *reinterpret_cast<const float4*>(&Bs[kk][tx*8]);
            float4 b1 = *reinterpret_cast<const float4*>(&Bs[kk][tx*8+4]);
            float a[8] = {a0.x,a0.y,a0.z,a0.w,a1.x,a1.y,a1.z,a1.w};
            float b[8] = {b0.x,b0.y,b0.z,b0.w,b1.x,b1.y,b1.z,b1.w};
#pragma unroll
            for (int i = 0; i < 8; i++)
#pragma unroll
                for (int j = 0; j < 8; j++) acc[i][j] += a[i] * b[j];
        }
        __syncthreads();
    }
    float4 bi0 = *reinterpret_cast<const float4*>(&bias[col0 + tx*8]);
    float4 bi1 = *reinterpret_cast<const float4*>(&bias[col0 + tx*8 + 4]);
#pragma unroll
    for (int i = 0; i < 8; i++) {
        int gm = row0 + ty*8 + i;
        if (gm < M) {
            float* cp = Cm + (size_t)gm*N + col0 + tx*8;
            float4 r0 = make_float4(acc[i][0]+bi0.x, acc[i][1]+bi0.y, acc[i][2]+bi0.z, acc[i][3]+bi0.w);
            float4 r1 = make_float4(acc[i][4]+bi1.x, acc[i][5]+bi1.y, acc[i][6]+bi1.z, acc[i][7]+bi1.w);
            *reinterpret_cast<float4*>(cp)     = r0;
            *reinterpret_cast<float4*>(cp + 4) = r1;
        }
    }
}

// ---------------- mini-attention path (flag-guarded; zero_w==0 => skipped) ----------------
__global__ void __launch_bounds__(256) build_tok(const float* __restrict__ mini_pos)
{
    if (g_flag == 0) return;
    int idx = blockIdx.x * blockDim.x + threadIdx.x;
    if (idx >= BB*NCOARSE*4*CC) return;
    int c = idx % CC;
    int r = (idx / CC) & 3;
    int g = idx / (4*CC);
    int b = g / NCOARSE;
    int cc = g - b*NCOARSE;
    int ci = cc / 7, cj = cc - ci*7;
    int di = r >> 1, dj = r & 1;
    int f = (2*ci + di)*14 + (2*cj + dj);
    g_tok[idx] = g_pe[(size_t)(b*NFINE + f)*CC + c] + mini_pos[r*CC + c];
}

__global__ void __launch_bounds__(128) mini_attn_kernel()
{
    if (g_flag == 0) return;
    int g = blockIdx.x;
    if (!g_m32[g]) return;
    __shared__ float q[4][CC];
    __shared__ float k[4][CC];
    __shared__ float att[4][4];
    int t = threadIdx.x;
    for (int idx = t; idx < 4*CC; idx += 128) {
        int r = idx / CC, c = idx - r*CC;
        q[r][c] = g_qkv[(size_t)(g*4 + r)*N3 + c];
        k[r][c] = g_qkv[(size_t)(g*4 + r)*N3 + CC + c];
    }
    __syncthreads();
    if (t < 16) {
        int qr = t >> 2, kr = t & 3;
        float s = 0.f;
        for (int c = 0; c < CC; c++) s += q[qr][c] * k[kr][c];
        att[qr][kr] = s * rsqrtf((float)CC);
    }
    __syncthreads();
    if (t < 4) {
        float mx = att[t][0];
        for (int j = 1; j < 4; j++) mx = fmaxf(mx, att[t][j]);
        float e[4], sum = 0.f;
        for (int j = 0; j < 4; j++) { e[j] = __expf(att[t][j] - mx); sum += e[j]; }
        for (int j = 0; j < 4; j++) att[t][j] = e[j] / sum;
    }
    __syncthreads();
    for (int idx = t; idx < 4*CC; idx += 128) {
        int r = idx / CC, c = idx - r*CC;
        float s = 0.f;
        for (int kr = 0; kr < 4; kr++)
            s += att[r][kr] * g_qkv[(size_t)(g*4 + kr)*N3 + 2*CC + c];
        g_o[(size_t)(g*4 + r)*CC + c] = s;
    }
}

__global__ void __launch_bounds__(256) mean_kernel()
{
    if (g_flag == 0) return;
    int idx = blockIdx.x * blockDim.x + threadIdx.x;
    if (idx >= BB*NCOARSE*CC) return;
    int g = idx / CC;
    int c = idx - g*CC;
    float s = 0.f;
    for (int r = 0; r < 4; r++) s += g_po[(size_t)(g*4 + r)*CC + c];
    g_mean[idx] = s * 0.25f;
}

// ---------------- final ragged assembly ----------------
__global__ void __launch_bounds__(256) assemble(
    const float* __restrict__ pos_fine, const float* __restrict__ pos_coarse,
    const float* __restrict__ cls_token, const float* __restrict__ mini_pos,
    float* __restrict__ out)
{
    int rid = blockIdx.x;
    int t = threadIdx.x;
    const int FINE = BB*NFINE, COARSE = BB*NCOARSE;
    if (rid < FINE) {
        int pos = g_finepos[rid];
        if (pos < 0) return;
        int f = rid % NFINE;
        const float* src = g_pe + (size_t)rid*CC;
        const float* pe  = pos_fine + (size_t)f*CC;
        float* dst = out + (size_t)pos*CC;
        for (int c = t; c < CC; c += 256) dst[c] = src[c] + pe[c];
    } else if (rid < FINE + COARSE) {
        int r = rid - FINE;
        int pos = g_coarsepos[r];
        if (pos < 0) return;
        int cc = r % NCOARSE;
        const float* src = g_cpe + (size_t)r*CC;
        const float* pc  = pos_coarse + (size_t)cc*CC;
        const float* zz  = g_z + (size_t)r*CC;
        int flag = g_flag;
        float* dst = out + (size_t)pos*CC;
        for (int c = t; c < CC; c += 256)
            dst[c] = src[c] + pc[c] + (flag ? zz[c] : 0.0f);
    } else {
        int b = rid - FINE - COARSE;
        int pos = g_cls[b];
        float* dst = out + (size_t)pos*CC;
        for (int c = t; c < CC; c += 256) dst[c] = cls_token[c] + mini_pos[c];
    }
}

// ---------------- launch ----------------
template <typename T>
static void* sym_addr(const T& sym)
{
    void* p = nullptr;
    cudaGetSymbolAddress(&p, sym);
    return p;
}

extern "C" void kernel_launch(void* const* d_in, const int* in_sizes, int n_in,
                              void* d_out, int out_size)
{
    const float* x         = (const float*)d_in[0];
    const float* entropy   = (const float*)d_in[1];
    const float* W_pe      = (const float*)d_in[2];
    const float* b_pe      = (const float*)d_in[3];
    const float* qkv_w     = (const float*)d_in[4];
    const float* qkv_b     = (const float*)d_in[5];
    const float* proj_w    = (const float*)d_in[6];
    const float* proj_b    = (const float*)d_in[7];
    const float* mini_pos  = (const float*)d_in[8];
    const float* zero_w    = (const float*)d_in[9];
    const float* zero_b    = (const float*)d_in[10];
    const float* cls_token = (const float*)d_in[11];
    const float* pos_fine  = (const float*)d_in[12];
    const float* pos_coarse= (const float*)d_in[13];
    float* out = (float*)d_out;

    float* p_patches = (float*)sym_addr(g_patches);
    float* p_pe      = (float*)sym_addr(g_pe);
    float* p_cpat    = (float*)sym_addr(g_cpat);
    float* p_cpe     = (float*)sym_addr(g_cpe);
    float* p_tok     = (float*)sym_addr(g_tok);
    float* p_qkv     = (float*)sym_addr(g_qkv);
    float* p_o       = (float*)sym_addr(g_o);
    float* p_po      = (float*)sym_addr(g_po);
    float* p_mean    = (float*)sym_addr(g_mean);
    float* p_z       = (float*)sym_addr(g_z);
    int*   p_flag    = (int*)  sym_addr(g_flag);

    // 1) masks, positions, zero_w flag, optional tail outputs
    mask_kernel<<<1, 512>>>(entropy, zero_w, zero_b, out, out_size);

    // 2) patch extraction
    extract_fine  <<<(BB*NFINE*KDIM   + 255)/256, 256>>>(x);
    extract_coarse<<<(BB*NCOARSE*KDIM + 255)/256, 256>>>(x);

    // 3) base patch embedding GEMMs
    sgemm_bias<<<dim3(CC/BN, (BB*NFINE   + BM-1)/BM), 256>>>(p_patches, W_pe, b_pe, p_pe,
                                                             BB*NFINE,   CC, KDIM, nullptr);
    sgemm_bias<<<dim3(CC/BN, (BB*NCOARSE + BM-1)/BM), 256>>>(p_cpat,    W_pe, b_pe, p_cpe,
                                                             BB*NCOARSE, CC, KDIM, nullptr);

    // 4) mini-attention residual path — early-exits entirely when zero_w == 0
    const int MT = BB*NCOARSE*4;   // 12544
    build_tok<<<(MT*CC + 255)/256, 256>>>(mini_pos);
    sgemm_bias<<<dim3(N3/BN, (MT + BM-1)/BM), 256>>>(p_tok, qkv_w, qkv_b, p_qkv, MT, N3, CC, p_flag);
    mini_attn_kernel<<<BB*NCOARSE, 128>>>();
    sgemm_bias<<<dim3(CC/BN, (MT + BM-1)/BM), 256>>>(p_o, proj_w, proj_b, p_po, MT, CC, CC, p_flag);
    mean_kernel<<<(BB*NCOARSE*CC + 255)/256, 256>>>();
    sgemm_bias<<<dim3(CC/BN, (BB*NCOARSE + BM-1)/BM), 256>>>(p_mean, zero_w, zero_b, p_z,
                                                             BB*NCOARSE, CC, CC, p_flag);

    // 5) ragged assembly (cls + fine + coarse rows)
    assemble<<<BB*NFINE + BB*NCOARSE + BB, 256>>>(pos_fine, pos_coarse, cls_token, mini_pos, out);
}

// round 3
// speedup vs baseline: 1.1663x; 1.1663x over previous
#include <cuda_runtime.h>
#include <cuda_bf16.h>
#include <mma.h>
#include <cstdint>

using namespace nvcuda;

// ---------------- problem constants ----------------
#define BB   64
#define CC   768
#define NFINE 196          // 14*14
#define NCOARSE 49         // 7*7
#define KDIM 768           // 3*16*16
#define N3   2304          // 3*C
#define FINE_ROWS   (BB*NFINE)     // 12544
#define COARSE_ROWS (BB*NCOARSE)   // 3136
#define ALL_ROWS    (FINE_ROWS + COARSE_ROWS)  // 15680

// ---------------- device scratch (static, no allocs) ----------------
__device__ float g_patches[ALL_ROWS*KDIM];     // fine then coarse patch vectors
__device__ float g_pe     [ALL_ROWS*CC];       // embeddings (fine rows then coarse rows)
__device__ float g_tok    [BB*NCOARSE*4*CC];   // mini-attn tokens
__device__ float g_qkv    [BB*NCOARSE*4*N3];   // qkv
__device__ float g_o      [BB*NCOARSE*4*CC];   // attn output
__device__ float g_po     [BB*NCOARSE*4*CC];   // proj output
__device__ float g_mean   [BB*NCOARSE*CC];     // mean over 4 tokens
__device__ float g_z      [BB*NCOARSE*CC];     // zero_conv residual
__device__ int   g_m32    [BB*NCOARSE];
__device__ int   g_finepos[BB*NFINE];
__device__ int   g_coarsepos[BB*NCOARSE];
__device__ int   g_seq[BB];
__device__ int   g_cls[BB];
__device__ int   g_total;
__device__ int   g_flag;                        // nonzero if zero_w/zero_b not all-zero

// ---------------- mask / positions / flag ----------------
__global__ void __launch_bounds__(512) mask_kernel(
    const float* __restrict__ e, const float* __restrict__ zw,
    const float* __restrict__ zb, float* __restrict__ out, int out_size)
{
    __shared__ int s_flag;
    __shared__ int s_nc[BB];
    __shared__ int s_cls[BB+1];
    int t = threadIdx.x;
    if (t == 0) s_flag = 0;
    __syncthreads();
    int nz = 0;
    for (int i = t; i < CC*CC; i += blockDim.x) nz |= (zw[i] != 0.0f);
    for (int i = t; i < CC;    i += blockDim.x) nz |= (zb[i] != 0.0f);
    if (nz) atomicOr(&s_flag, 1);

    if (t < BB) {
        int b = t, nc = 0;
        const float* eb = e + b*NFINE;
        for (int cc = 0; cc < NCOARSE; cc++) {
            int ci = cc / 7, cj = cc % 7;
            float m = (eb[(2*ci)*14 + 2*cj]   + eb[(2*ci)*14 + 2*cj+1] +
                       eb[(2*ci+1)*14 + 2*cj] + eb[(2*ci+1)*14 + 2*cj+1]) * 0.25f;
            int sel = m < 0.5f;
            g_m32[b*NCOARSE + cc] = sel;
            nc += sel;
        }
        s_nc[t] = nc;
    }
    __syncthreads();
    if (t == 0) {
        int acc = 0;
        for (int b = 0; b < BB; b++) {
            s_cls[b] = acc;
            g_cls[b] = acc;
            int nc = s_nc[b];
            int seq = 1 + 4*(NCOARSE - nc) + nc;
            g_seq[b] = seq;
            acc += seq;
        }
        g_total = acc;
        s_cls[BB] = acc;
        g_flag = s_flag;
    }
    __syncthreads();
    if (t < BB) {
        int b = t;
        int base = s_cls[b];
        int rank = 0;
        for (int f = 0; f < NFINE; f++) {
            int i = f / 14, j = f % 14;
            int sel = g_m32[b*NCOARSE + (i>>1)*7 + (j>>1)];
            g_finepos[b*NFINE + f] = sel ? -1 : (base + 1 + rank);
            rank += !sel;
        }
        int crank = 0;
        for (int cc = 0; cc < NCOARSE; cc++) {
            int sel = g_m32[b*NCOARSE + cc];
            g_coarsepos[b*NCOARSE + cc] = sel ? (base + 1 + rank + crank) : -1;
            crank += sel;
        }
    }
    __syncthreads();
    // optional tail: seq_lengths + cls_loc appended as floats
    long long total = s_cls[BB];
    long long need = total * CC + 2*BB;
    if ((long long)out_size == need && t < BB) {
        out[total*CC + t]      = (float)g_seq[t];
        out[total*CC + BB + t] = (float)g_cls[t];
    }
}

// ---------------- patch extraction ----------------
__global__ void __launch_bounds__(256) extract_fine(const float* __restrict__ x)
{
    int idx = blockIdx.x * blockDim.x + threadIdx.x;
    if (idx >= FINE_ROWS*KDIM) return;
    int row = idx / KDIM;
    int k   = idx - row * KDIM;
    int c  = k >> 8;            // /256
    int pi = (k >> 4) & 15;
    int pj = k & 15;
    int b = row / NFINE;
    int f = row - b * NFINE;
    int i = f / 14, j = f - i*14;
    g_patches[idx] = x[((size_t)(b*3 + c)*224 + i*16 + pi)*224 + j*16 + pj];
}

__global__ void __launch_bounds__(256) extract_coarse(const float* __restrict__ x)
{
    int idx = blockIdx.x * blockDim.x + threadIdx.x;
    if (idx >= COARSE_ROWS*KDIM) return;
    int row = idx / KDIM;
    int k   = idx - row * KDIM;
    int c  = k >> 8;
    int pi = (k >> 4) & 15;
    int pj = k & 15;
    int b  = row / NCOARSE;
    int cc = row - b * NCOARSE;
    int ci = cc / 7, cj = cc - ci*7;
    int y = (ci*16 + pi) * 2;
    int xx = (cj*16 + pj) * 2;
    const float* base = x + ((size_t)(b*3 + c)*224 + y)*224 + xx;
    g_patches[(size_t)FINE_ROWS*KDIM + idx] =
        (base[0] + base[1] + base[224] + base[225]) * 0.25f;
}

// ---------------- TF32 tensor-core GEMM: C = A(MxK) @ B(KxN) (no bias) ----------------
// 128x128 block tile, BK=32, 8 warps each computing 32x64 via 2x4 wmma 16x16x8 frags.
#define TBM 128
#define TBN 128
#define TBK 32
__global__ void __launch_bounds__(256) tf32_gemm(
    const float* __restrict__ A, const float* __restrict__ Bm,
    float* __restrict__ Cm, int M, int N, int K)
{
    __shared__ float As[TBM][TBK + 4];   // row-major A tile
    __shared__ float Bs[TBK][TBN + 4];   // row-major B tile

    int tid  = threadIdx.x;
    int warp = tid >> 5;
    int wr   = warp >> 1;     // 0..3  (row group of 32)
    int wc   = warp & 1;      // 0..1  (col group of 64)
    int row0 = blockIdx.y * TBM;
    int col0 = blockIdx.x * TBN;

    wmma::fragment<wmma::accumulator, 16, 16, 8, float> acc[2][4];
#pragma unroll
    for (int i = 0; i < 2; i++)
#pragma unroll
        for (int j = 0; j < 4; j++) wmma::fill_fragment(acc[i][j], 0.0f);

    for (int k0 = 0; k0 < K; k0 += TBK) {
        // load A tile: 128x32 floats = 1024 float4, 4 per thread
#pragma unroll
        for (int it = 0; it < 4; it++) {
            int lin = tid + it * 256;          // 0..1023
            int r   = lin >> 3;                // 0..127
            int c4  = (lin & 7) << 2;          // 0,4,...,28
            int gm  = row0 + r;
            float4 v = make_float4(0.f, 0.f, 0.f, 0.f);
            if (gm < M) v = *reinterpret_cast<const float4*>(&A[(size_t)gm*K + k0 + c4]);
            *reinterpret_cast<float4*>(&As[r][c4]) = v;
        }
        // load B tile: 32x128 floats = 1024 float4, 4 per thread
#pragma unroll
        for (int it = 0; it < 4; it++) {
            int lin = tid + it * 256;
            int r   = lin >> 5;                // 0..31
            int c4  = (lin & 31) << 2;         // 0..124
            float4 v = *reinterpret_cast<const float4*>(&Bm[(size_t)(k0 + r)*N + col0 + c4]);
            *reinterpret_cast<float4*>(&Bs[r][c4]) = v;
        }
        __syncthreads();

#pragma unroll
        for (int kk = 0; kk < TBK; kk += 8) {
            wmma::fragment<wmma::matrix_a, 16, 16, 8, wmma::precision::tf32, wmma::row_major> af[2];
            wmma::fragment<wmma::matrix_b, 16, 16, 8, wmma::precision::tf32, wmma::row_major> bf[4];
#pragma unroll
            for (int i = 0; i < 2; i++) {
                wmma::load_matrix_sync(af[i], &As[wr*32 + i*16][kk], TBK + 4);
#pragma unroll
                for (int e = 0; e < af[i].num_elements; e++)
                    af[i].x[e] = wmma::__float_to_tf32(af[i].x[e]);
            }
#pragma unroll
            for (int j = 0; j < 4; j++) {
                wmma::load_matrix_sync(bf[j], &Bs[kk][wc*64 + j*16], TBN + 4);
#pragma unroll
                for (int e = 0; e < bf[j].num_elements; e++)
                    bf[j].x[e] = wmma::__float_to_tf32(bf[j].x[e]);
            }
#pragma unroll
            for (int i = 0; i < 2; i++)
#pragma unroll
                for (int j = 0; j < 4; j++)
                    wmma::mma_sync(acc[i][j], af[i], bf[j], acc[i][j]);
        }
        __syncthreads();
    }

    // store (M is a multiple of 16, so fragments are either fully in or out)
#pragma unroll
    for (int i = 0; i < 2; i++) {
        int rbase = row0 + wr*32 + i*16;
        if (rbase + 16 <= M) {
#pragma unroll
            for (int j = 0; j < 4; j++) {
                float* cp = Cm + (size_t)rbase*N + col0 + wc*64 + j*16;
                wmma::store_matrix_sync(cp, acc[i][j], N, wmma::mem_row_major);
            }
        }
    }
}

// ---------------- fp32 SGEMM (kept for the flag-guarded mini-attn path) ----------------
#define BM 128
#define BN 128
#define BK 8
__global__ void __launch_bounds__(256) sgemm_bias(
    const float* __restrict__ A, const float* __restrict__ Bm,
    const float* __restrict__ bias, float* __restrict__ Cm,
    int M, int N, int K, const int* flagptr)
{
    if (flagptr && *flagptr == 0) return;
    __shared__ float As[BK][BM];
    __shared__ float Bs[BK][BN];
    int tid = threadIdx.x;
    int row0 = blockIdx.y * BM;
    int col0 = blockIdx.x * BN;
    int tx = tid & 15;
    int ty = tid >> 4;
    float acc[8][8];
#pragma unroll
    for (int i = 0; i < 8; i++)
#pragma unroll
        for (int j = 0; j < 8; j++) acc[i][j] = 0.0f;

    int aRow = tid >> 1;
    int aCol = (tid & 1) * 4;
    int bRow = tid >> 5;
    int bCol = (tid & 31) * 4;

    for (int k0 = 0; k0 < K; k0 += BK) {
        float4 av = make_float4(0.f, 0.f, 0.f, 0.f);
        int gm = row0 + aRow;
        if (gm < M) av = *reinterpret_cast<const float4*>(&A[(size_t)gm*K + k0 + aCol]);
        As[aCol+0][aRow] = av.x;
        As[aCol+1][aRow] = av.y;
        As[aCol+2][aRow] = av.z;
        As[aCol+3][aRow] = av.w;
        float4 bv = *reinterpret_cast<const float4*>(&Bm[(size_t)(k0 + bRow)*N + col0 + bCol]);
        *reinterpret_cast<float4*>(&Bs[bRow][bCol]) = bv;
        __syncthreads();
#pragma unroll
        for (int kk = 0; kk < BK; kk++) {
            float4 a0 = *reinterpret_cast<const float4*>(&As[kk][ty*8]);
            float4 a1 = *reinterpret_cast<const float4*>(&As[kk][ty*8+4]);
            float4 b0 = *reinterpret_cast<const float4*>(&Bs[kk][tx*8]);
            float4 b1 = *reinterpret_cast<const float4*>(&Bs[kk][tx*8+4]);
            float a[8] = {a0.x,a0.y,a0.z,a0.w,a1.x,a1.y,a1.z,a1.w};
            float b[8] = {b0.x,b0.y,b0.z,b0.w,b1.x,b1.y,b1.z,b1.w};
#pragma unroll
            for (int i = 0; i < 8; i++)
#pragma unroll
                for (int j = 0; j < 8; j++) acc[i][j] += a[i] * b[j];
        }
        __syncthreads();
    }
    float4 bi0 = *reinterpret_cast<const float4*>(&bias[col0 + tx*8]);
    float4 bi1 = *reinterpret_cast<const float4*>(&bias[col0 + tx*8 + 4]);
#pragma unroll
    for (int i = 0; i < 8; i++) {
        int gm = row0 + ty*8 + i;
        if (gm < M) {
            float* cp = Cm + (size_t)gm*N + col0 + tx*8;
            float4 r0 = make_float4(acc[i][0]+bi0.x, acc[i][1]+bi0.y, acc[i][2]+bi0.z, acc[i][3]+bi0.w);
            float4 r1 = make_float4(acc[i][4]+bi1.x, acc[i][5]+bi1.y, acc[i][6]+bi1.z, acc[i][7]+bi1.w);
            *reinterpret_cast<float4*>(cp)     = r0;
            *reinterpret_cast<float4*>(cp + 4) = r1;
        }
    }
}

// ---------------- mini-attention path (flag-guarded; zero_w==0 => skipped) ----------------
__global__ void __launch_bounds__(256) build_tok(const float* __restrict__ mini_pos,
                                                 const float* __restrict__ b_pe)
{
    if (g_flag == 0) return;
    int idx = blockIdx.x * blockDim.x + threadIdx.x;
    if (idx >= BB*NCOARSE*4*CC) return;
    int c = idx % CC;
    int r = (idx / CC) & 3;
    int g = idx / (4*CC);
    int b = g / NCOARSE;
    int cc = g - b*NCOARSE;
    int ci = cc / 7, cj = cc - ci*7;
    int di = r >> 1, dj = r & 1;
    int f = (2*ci + di)*14 + (2*cj + dj);
    g_tok[idx] = g_pe[(size_t)(b*NFINE + f)*CC + c] + b_pe[c] + mini_pos[r*CC + c];
}

__global__ void __launch_bounds__(128) mini_attn_kernel()
{
    if (g_flag == 0) return;
    int g = blockIdx.x;
    if (!g_m32[g]) return;
    __shared__ float q[4][CC];
    __shared__ float k[4][CC];
    __shared__ float att[4][4];
    int t = threadIdx.x;
    for (int idx = t; idx < 4*CC; idx += 128) {
        int r = idx / CC, c = idx - r*CC;
        q[r][c] = g_qkv[(size_t)(g*4 + r)*N3 + c];
        k[r][c] = g_qkv[(size_t)(g*4 + r)*N3 + CC + c];
    }
    __syncthreads();
    if (t < 16) {
        int qr = t >> 2, kr = t & 3;
        float s = 0.f;
        for (int c = 0; c < CC; c++) s += q[qr][c] * k[kr][c];
        att[qr][kr] = s * rsqrtf((float)CC);
    }
    __syncthreads();
    if (t < 4) {
        float mx = att[t][0];
        for (int j = 1; j < 4; j++) mx = fmaxf(mx, att[t][j]);
        float e[4], sum = 0.f;
        for (int j = 0; j < 4; j++) { e[j] = __expf(att[t][j] - mx); sum += e[j]; }
        for (int j = 0; j < 4; j++) att[t][j] = e[j] / sum;
    }
    __syncthreads();
    for (int idx = t; idx < 4*CC; idx += 128) {
        int r = idx / CC, c = idx - r*CC;
        float s = 0.f;
        for (int kr = 0; kr < 4; kr++)
            s += att[r][kr] * g_qkv[(size_t)(g*4 + kr)*N3 + 2*CC + c];
        g_o[(size_t)(g*4 + r)*CC + c] = s;
    }
}

__global__ void __launch_bounds__(256) mean_kernel()
{
    if (g_flag == 0) return;
    int idx = blockIdx.x * blockDim.x + threadIdx.x;
    if (idx >= BB*NCOARSE*CC) return;
    int g = idx / CC;
    int c = idx - g*CC;
    float s = 0.f;
    for (int r = 0; r < 4; r++) s += g_po[(size_t)(g*4 + r)*CC + c];
    g_mean[idx] = s * 0.25f;
}

// ---------------- final ragged assembly (bias folded in) ----------------
__global__ void __launch_bounds__(256) assemble(
    const float* __restrict__ pos_fine, const float* __restrict__ pos_coarse,
    const float* __restrict__ cls_token, const float* __restrict__ mini_pos,
    const float* __restrict__ b_pe, float* __restrict__ out)
{
    int rid = blockIdx.x;
    int t = threadIdx.x;
    if (rid < FINE_ROWS) {
        int pos = g_finepos[rid];
        if (pos < 0) return;
        int f = rid % NFINE;
        const float* src = g_pe + (size_t)rid*CC;
        const float* pe  = pos_fine + (size_t)f*CC;
        float* dst = out + (size_t)pos*CC;
        for (int c = t; c < CC; c += 256) dst[c] = src[c] + b_pe[c] + pe[c];
    } else if (rid < FINE_ROWS + COARSE_ROWS) {
        int r = rid - FINE_ROWS;
        int pos = g_coarsepos[r];
        if (pos < 0) return;
        int cc = r % NCOARSE;
        const float* src = g_pe + (size_t)(FINE_ROWS + r)*CC;
        const float* pc  = pos_coarse + (size_t)cc*CC;
        const float* zz  = g_z + (size_t)r*CC;
        int flag = g_flag;
        float* dst = out + (size_t)pos*CC;
        for (int c = t; c < CC; c += 256)
            dst[c] = src[c] + b_pe[c] + pc[c] + (flag ? zz[c] : 0.0f);
    } else {
        int b = rid - FINE_ROWS - COARSE_ROWS;
        int pos = g_cls[b];
        float* dst = out + (size_t)pos*CC;
        for (int c = t; c < CC; c += 256) dst[c] = cls_token[c] + mini_pos[c];
    }
}

// ---------------- launch ----------------
template <typename T>
static void* sym_addr(const T& sym)
{
    void* p = nullptr;
    cudaGetSymbolAddress(&p, sym);
    return p;
}

extern "C" void kernel_launch(void* const* d_in, const int* in_sizes, int n_in,
                              void* d_out, int out_size)
{
    const float* x         = (const float*)d_in[0];
    const float* entropy   = (const float*)d_in[1];
    const float* W_pe      = (const float*)d_in[2];
    const float* b_pe      = (const float*)d_in[3];
    const float* qkv_w     = (const float*)d_in[4];
    const float* qkv_b     = (const float*)d_in[5];
    const float* proj_w    = (const float*)d_in[6];
    const float* proj_b    = (const float*)d_in[7];
    const float* mini_pos  = (const float*)d_in[8];
    const float* zero_w    = (const float*)d_in[9];
    const float* zero_b    = (const float*)d_in[10];
    const float* cls_token = (const float*)d_in[11];
    const float* pos_fine  = (const float*)d_in[12];
    const float* pos_coarse= (const float*)d_in[13];
    float* out = (float*)d_out;

    float* p_patches = (float*)sym_addr(g_patches);
    float* p_pe      = (float*)sym_addr(g_pe);
    float* p_tok     = (float*)sym_addr(g_tok);
    float* p_qkv     = (float*)sym_addr(g_qkv);
    float* p_o       = (float*)sym_addr(g_o);
    float* p_po      = (float*)sym_addr(g_po);
    float* p_mean    = (float*)sym_addr(g_mean);
    float* p_z       = (float*)sym_addr(g_z);
    int*   p_flag    = (int*)  sym_addr(g_flag);

    // 1) masks, positions, zero_w flag, optional tail outputs
    mask_kernel<<<1, 512>>>(entropy, zero_w, zero_b, out, out_size);

    // 2) patch extraction (fine rows then coarse rows in one A buffer)
    extract_fine  <<<(FINE_ROWS*KDIM   + 255)/256, 256>>>(x);
    extract_coarse<<<(COARSE_ROWS*KDIM + 255)/256, 256>>>(x);

    // 3) combined patch-embed GEMM on tensor cores (TF32), no bias
    tf32_gemm<<<dim3(CC/TBN, (ALL_ROWS + TBM-1)/TBM), 256>>>(p_patches, W_pe, p_pe,
                                                             ALL_ROWS, CC, KDIM);

    // 4) mini-attention residual path — early-exits entirely when zero_w == 0
    const int MT = BB*NCOARSE*4;   // 12544
    build_tok<<<(MT*CC + 255)/256, 256>>>(mini_pos, b_pe);
    sgemm_bias<<<dim3(N3/BN, (MT + BM-1)/BM), 256>>>(p_tok, qkv_w, qkv_b, p_qkv, MT, N3, CC, p_flag);
    mini_attn_kernel<<<BB*NCOARSE, 128>>>();
    sgemm_bias<<<dim3(CC/BN, (MT + BM-1)/BM), 256>>>(p_o, proj_w, proj_b, p_po, MT, CC, CC, p_flag);
    mean_kernel<<<(BB*NCOARSE*CC + 255)/256, 256>>>();
    sgemm_bias<<<dim3(CC/BN, (COARSE_ROWS + BM-1)/BM), 256>>>(p_mean, zero_w, zero_b, p_z,
                                                              COARSE_ROWS, CC, CC, p_flag);

    // 5) ragged assembly (cls + fine + coarse rows), b_pe folded in
    assemble<<<FINE_ROWS + COARSE_ROWS + BB, 256>>>(pos_fine, pos_coarse, cls_token,
                                                    mini_pos, b_pe, out);
}

// round 4
// speedup vs baseline: 1.8726x; 1.6056x over previous
#include <cuda_runtime.h>
#include <cuda_bf16.h>
#include <mma.h>
#include <cstdint>

using namespace nvcuda;

// ---------------- problem constants ----------------
#define BB   64
#define CC   768
#define NFINE 196          // 14*14
#define NCOARSE 49         // 7*7
#define KDIM 768           // 3*16*16
#define N3   2304          // 3*C
#define FINE_ROWS   (BB*NFINE)     // 12544
#define COARSE_ROWS (BB*NCOARSE)   // 3136
#define ALL_ROWS    (FINE_ROWS + COARSE_ROWS)  // 15680

// ---------------- device scratch (static, no allocs) ----------------
__device__ float g_cpat   [COARSE_ROWS*KDIM];  // coarse patch vectors (3136,768)
__device__ float g_pe     [ALL_ROWS*CC];       // embeddings (fine rows then coarse rows)
__device__ float g_tok    [BB*NCOARSE*4*CC];   // mini-attn tokens
__device__ float g_qkv    [BB*NCOARSE*4*N3];   // qkv
__device__ float g_o      [BB*NCOARSE*4*CC];   // attn output
__device__ float g_po     [BB*NCOARSE*4*CC];   // proj output
__device__ float g_mean   [BB*NCOARSE*CC];     // mean over 4 tokens
__device__ float g_z      [BB*NCOARSE*CC];     // zero_conv residual
__device__ int   g_m32    [BB*NCOARSE];
__device__ int   g_finepos[BB*NFINE];
__device__ int   g_coarsepos[BB*NCOARSE];
__device__ int   g_seq[BB];
__device__ int   g_cls[BB];
__device__ int   g_total;
__device__ int   g_flag;                        // nonzero if zero_w/zero_b not all-zero

// ---------------- helpers ----------------
__device__ __forceinline__ uint32_t smem_u32(const void* p)
{
    uint32_t a;
    asm("{ .reg .u64 t; cvta.to.shared.u64 t, %1; cvt.u32.u64 %0, t; }" : "=r"(a) : "l"(p));
    return a;
}
__device__ __forceinline__ void cp_async16(uint32_t dst, const void* src, bool pred)
{
    int sz = pred ? 16 : 0;
    asm volatile("cp.async.cg.shared.global [%0], [%1], 16, %2;\n"
                 :: "r"(dst), "l"(src), "r"(sz));
}
__device__ __forceinline__ void cp_commit()  { asm volatile("cp.async.commit_group;\n"); }
__device__ __forceinline__ void cp_wait0()   { asm volatile("cp.async.wait_group 0;\n"); }

// ---------------- zero_w flag scan (parallel) ----------------
__global__ void __launch_bounds__(256) flag_scan(
    const float* __restrict__ zw, const float* __restrict__ zb)
{
    int nz = 0;
    for (int i = blockIdx.x*blockDim.x + threadIdx.x; i < CC*CC; i += gridDim.x*blockDim.x)
        nz |= (zw[i] != 0.0f);
    if (blockIdx.x == 0)
        for (int i = threadIdx.x; i < CC; i += blockDim.x) nz |= (zb[i] != 0.0f);
    if (__syncthreads_or(nz) && threadIdx.x == 0) atomicOr(&g_flag, 1);
}

// ---------------- mask / positions ----------------
__global__ void __launch_bounds__(128) mask_kernel(
    const float* __restrict__ e, float* __restrict__ out, int out_size)
{
    __shared__ int s_nc[BB];
    __shared__ int s_cls[BB+1];
    int t = threadIdx.x;
    if (t < BB) {
        int b = t, nc = 0;
        const float* eb = e + b*NFINE;
        for (int cc = 0; cc < NCOARSE; cc++) {
            int ci = cc / 7, cj = cc % 7;
            float m = (eb[(2*ci)*14 + 2*cj]   + eb[(2*ci)*14 + 2*cj+1] +
                       eb[(2*ci+1)*14 + 2*cj] + eb[(2*ci+1)*14 + 2*cj+1]) * 0.25f;
            int sel = m < 0.5f;
            g_m32[b*NCOARSE + cc] = sel;
            nc += sel;
        }
        s_nc[t] = nc;
    }
    __syncthreads();
    if (t == 0) {
        int acc = 0;
        for (int b = 0; b < BB; b++) {
            s_cls[b] = acc;
            g_cls[b] = acc;
            int nc = s_nc[b];
            int seq = 1 + 4*(NCOARSE - nc) + nc;
            g_seq[b] = seq;
            acc += seq;
        }
        g_total = acc;
        s_cls[BB] = acc;
    }
    __syncthreads();
    if (t < BB) {
        int b = t;
        int base = s_cls[b];
        int rank = 0;
        for (int f = 0; f < NFINE; f++) {
            int i = f / 14, j = f % 14;
            int sel = g_m32[b*NCOARSE + (i>>1)*7 + (j>>1)];
            g_finepos[b*NFINE + f] = sel ? -1 : (base + 1 + rank);
            rank += !sel;
        }
        int crank = 0;
        for (int cc = 0; cc < NCOARSE; cc++) {
            int sel = g_m32[b*NCOARSE + cc];
            g_coarsepos[b*NCOARSE + cc] = sel ? (base + 1 + rank + crank) : -1;
            crank += sel;
        }
    }
    __syncthreads();
    // optional tail: seq_lengths + cls_loc appended as floats
    long long total = s_cls[BB];
    long long need = total * CC + 2*BB;
    if ((long long)out_size == need && t < BB) {
        out[total*CC + t]      = (float)g_seq[t];
        out[total*CC + BB + t] = (float)g_cls[t];
    }
}

// ---------------- coarse patch extraction (2x2 mean of x) ----------------
__global__ void __launch_bounds__(256) extract_coarse(const float* __restrict__ x)
{
    int idx = blockIdx.x * blockDim.x + threadIdx.x;
    if (idx >= COARSE_ROWS*KDIM) return;
    int row = idx / KDIM;
    int k   = idx - row * KDIM;
    int c  = k >> 8;
    int pi = (k >> 4) & 15;
    int pj = k & 15;
    int b  = row / NCOARSE;
    int cc = row - b * NCOARSE;
    int ci = cc / 7, cj = cc - ci*7;
    int y = (ci*16 + pi) * 2;
    int xx = (cj*16 + pj) * 2;
    const float* base = x + ((size_t)(b*3 + c)*224 + y)*224 + xx;
    g_cpat[idx] = (base[0] + base[1] + base[224] + base[225]) * 0.25f;
}

// ---------------- TF32 tensor-core GEMM, double-buffered cp.async ----------------
// C(ALL_ROWS x 768) = Apatch @ W_pe. A rows < FINE_ROWS are gathered straight
// from x (16-float runs are contiguous); rows >= FINE_ROWS come from g_cpat.
#define TBM 128
#define TBN 128
#define TBK 16
__global__ void __launch_bounds__(256, 2) pe_gemm(
    const float* __restrict__ x, const float* __restrict__ cpat,
    const float* __restrict__ Bm, float* __restrict__ Cm)
{
    __shared__ float As[2][TBM][TBK + 4];
    __shared__ float Bs[2][TBK][TBN + 4];

    const int M = ALL_ROWS, N = CC, K = KDIM;
    int tid  = threadIdx.x;
    int warp = tid >> 5;
    int wr   = warp >> 1;     // 0..3
    int wc   = warp & 1;      // 0..1
    int row0 = blockIdx.y * TBM;
    int col0 = blockIdx.x * TBN;

    // per-thread A-load coords (2 float4 per stage)
    int ar[2], ac4[2];
    const float* abase[2];   // base address ignoring k (recomputed per k0 for fine)
    int afine[2], ab[2], ai[2], aj[2];
#pragma unroll
    for (int it = 0; it < 2; it++) {
        int lin = tid + it*256;          // 0..511
        int r   = lin >> 2;              // 0..127
        int c4  = (lin & 3) << 2;        // 0,4,8,12
        ar[it] = r; ac4[it] = c4;
        int gm = row0 + r;
        int gmc = gm < M ? gm : M-1;
        afine[it] = (gmc < FINE_ROWS);
        if (afine[it]) {
            int b = gmc / NFINE;
            int f = gmc - b*NFINE;
            ab[it] = b; ai[it] = f / 14; aj[it] = f - (f/14)*14;
        } else {
            abase[it] = cpat + (size_t)(gmc - FINE_ROWS)*KDIM;
        }
    }
    // B-load coords (2 float4 per stage)
    int br[2], bc4[2];
#pragma unroll
    for (int it = 0; it < 2; it++) {
        int lin = tid + it*256;
        br[it]  = lin >> 5;              // 0..15
        bc4[it] = (lin & 31) << 2;       // 0..124
    }

    wmma::fragment<wmma::accumulator, 16, 16, 8, float> acc[2][4];
#pragma unroll
    for (int i = 0; i < 2; i++)
#pragma unroll
        for (int j = 0; j < 4; j++) wmma::fill_fragment(acc[i][j], 0.0f);

    auto load_stage = [&](int buf, int k0) {
#pragma unroll
        for (int it = 0; it < 2; it++) {
            int gm = row0 + ar[it];
            bool pred = gm < M;
            const float* src;
            if (afine[it]) {
                int kc = k0 + ac4[it];
                int c  = kc >> 8;
                int pi = (kc >> 4) & 15;
                int pj = kc & 15;
                src = x + ((size_t)(ab[it]*3 + c)*224 + ai[it]*16 + pi)*224 + aj[it]*16 + pj;
            } else {
                src = abase[it] + k0 + ac4[it];
            }
            cp_async16(smem_u32(&As[buf][ar[it]][ac4[it]]), src, pred);
        }
#pragma unroll
        for (int it = 0; it < 2; it++) {
            const float* src = Bm + (size_t)(k0 + br[it])*N + col0 + bc4[it];
            cp_async16(smem_u32(&Bs[buf][br[it]][bc4[it]]), src, true);
        }
        cp_commit();
    };

    load_stage(0, 0);
    const int nK = K / TBK;   // 48
    for (int kt = 0; kt < nK; kt++) {
        int cur = kt & 1;
        cp_wait0();
        __syncthreads();
        if (kt + 1 < nK) load_stage(cur ^ 1, (kt+1)*TBK);

#pragma unroll
        for (int kk = 0; kk < TBK; kk += 8) {
            wmma::fragment<wmma::matrix_a, 16, 16, 8, wmma::precision::tf32, wmma::row_major> af[2];
            wmma::fragment<wmma::matrix_b, 16, 16, 8, wmma::precision::tf32, wmma::row_major> bf[4];
#pragma unroll
            for (int i = 0; i < 2; i++) {
                wmma::load_matrix_sync(af[i], &As[cur][wr*32 + i*16][kk], TBK + 4);
#pragma unroll
                for (int e = 0; e < af[i].num_elements; e++)
                    af[i].x[e] = wmma::__float_to_tf32(af[i].x[e]);
            }
#pragma unroll
            for (int j = 0; j < 4; j++) {
                wmma::load_matrix_sync(bf[j], &Bs[cur][kk][wc*64 + j*16], TBN + 4);
#pragma unroll
                for (int e = 0; e < bf[j].num_elements; e++)
                    bf[j].x[e] = wmma::__float_to_tf32(bf[j].x[e]);
            }
#pragma unroll
            for (int i = 0; i < 2; i++)
#pragma unroll
                for (int j = 0; j < 4; j++)
                    wmma::mma_sync(acc[i][j], af[i], bf[j], acc[i][j]);
        }
        __syncthreads();
    }

#pragma unroll
    for (int i = 0; i < 2; i++) {
        int rbase = row0 + wr*32 + i*16;
        if (rbase + 16 <= M) {
#pragma unroll
            for (int j = 0; j < 4; j++) {
                float* cp = Cm + (size_t)rbase*N + col0 + wc*64 + j*16;
                wmma::store_matrix_sync(cp, acc[i][j], N, wmma::mem_row_major);
            }
        }
    }
}

// ---------------- fp32 SGEMM (kept for the flag-guarded mini-attn path) ----------------
#define BM 128
#define BN 128
#define BK 8
__global__ void __launch_bounds__(256) sgemm_bias(
    const float* __restrict__ A, const float* __restrict__ Bm,
    const float* __restrict__ bias, float* __restrict__ Cm,
    int M, int N, int K, const int* flagptr)
{
    if (flagptr && *flagptr == 0) return;
    __shared__ float As[BK][BM];
    __shared__ float Bs[BK][BN];
    int tid = threadIdx.x;
    int row0 = blockIdx.y * BM;
    int col0 = blockIdx.x * BN;
    int tx = tid & 15;
    int ty = tid >> 4;
    float acc[8][8];
#pragma unroll
    for (int i = 0; i < 8; i++)
#pragma unroll
        for (int j = 0; j < 8; j++) acc[i][j] = 0.0f;

    int aRow = tid >> 1;
    int aCol = (tid & 1) * 4;
    int bRow = tid >> 5;
    int bCol = (tid & 31) * 4;

    for (int k0 = 0; k0 < K; k0 += BK) {
        float4 av = make_float4(0.f, 0.f, 0.f, 0.f);
        int gm = row0 + aRow;
        if (gm < M) av = *reinterpret_cast<const float4*>(&A[(size_t)gm*K + k0 + aCol]);
        As[aCol+0][aRow] = av.x;
        As[aCol+1][aRow] = av.y;
        As[aCol+2][aRow] = av.z;
        As[aCol+3][aRow] = av.w;
        float4 bv = *reinterpret_cast<const float4*>(&Bm[(size_t)(k0 + bRow)*N + col0 + bCol]);
        *reinterpret_cast<float4*>(&Bs[bRow][bCol]) = bv;
        __syncthreads();
#pragma unroll
        for (int kk = 0; kk < BK; kk++) {
            float4 a0 = *reinterpret_cast<const float4*>(&As[kk][ty*8]);
            float4 a1 = *reinterpret_cast<const float4*>(&As[kk][ty*8+4]);
            float4 b0 = *reinterpret_cast<const float4*>(&Bs[kk][tx*8]);
            float4 b1 = *reinterpret_cast<const float4*>(&Bs[kk][tx*8+4]);
            float a[8] = {a0.x,a0.y,a0.z,a0.w,a1.x,a1.y,a1.z,a1.w};
            float b[8] = {b0.x,b0.y,b0.z,b0.w,b1.x,b1.y,b1.z,b1.w};
#pragma unroll
            for (int i = 0; i < 8; i++)
#pragma unroll
                for (int j = 0; j < 8; j++) acc[i][j] += a[i] * b[j];
        }
        __syncthreads();
    }
    float4 bi0 = *reinterpret_cast<const float4*>(&bias[col0 + tx*8]);
    float4 bi1 = *reinterpret_cast<const float4*>(&bias[col0 + tx*8 + 4]);
#pragma unroll
    for (int i = 0; i < 8; i++) {
        int gm = row0 + ty*8 + i;
        if (gm < M) {
            float* cp = Cm + (size_t)gm*N + col0 + tx*8;
            float4 r0 = make_float4(acc[i][0]+bi0.x, acc[i][1]+bi0.y, acc[i][2]+bi0.z, acc[i][3]+bi0.w);
            float4 r1 = make_float4(acc[i][4]+bi1.x, acc[i][5]+bi1.y, acc[i][6]+bi1.z, acc[i][7]+bi1.w);
            *reinterpret_cast<float4*>(cp)     = r0;
            *reinterpret_cast<float4*>(cp + 4) = r1;
        }
    }
}

// ---------------- mini-attention path (flag-guarded; zero_w==0 => skipped) ----------------
__global__ void __launch_bounds__(256) build_tok(const float* __restrict__ mini_pos,
                                                 const float* __restrict__ b_pe)
{
    if (g_flag == 0) return;
    for (int idx = blockIdx.x*blockDim.x + threadIdx.x; idx < BB*NCOARSE*4*CC;
         idx += gridDim.x*blockDim.x) {
        int c = idx % CC;
        int r = (idx / CC) & 3;
        int g = idx / (4*CC);
        int b = g / NCOARSE;
        int cc = g - b*NCOARSE;
        int ci = cc / 7, cj = cc - ci*7;
        int di = r >> 1, dj = r & 1;
        int f = (2*ci + di)*14 + (2*cj + dj);
        g_tok[idx] = g_pe[(size_t)(b*NFINE + f)*CC + c] + b_pe[c] + mini_pos[r*CC + c];
    }
}

__global__ void __launch_bounds__(128) mini_attn_kernel()
{
    if (g_flag == 0) return;
    int g = blockIdx.x;
    if (!g_m32[g]) return;
    __shared__ float q[4][CC];
    __shared__ float k[4][CC];
    __shared__ float att[4][4];
    int t = threadIdx.x;
    for (int idx = t; idx < 4*CC; idx += 128) {
        int r = idx / CC, c = idx - r*CC;
        q[r][c] = g_qkv[(size_t)(g*4 + r)*N3 + c];
        k[r][c] = g_qkv[(size_t)(g*4 + r)*N3 + CC + c];
    }
    __syncthreads();
    if (t < 16) {
        int qr = t >> 2, kr = t & 3;
        float s = 0.f;
        for (int c = 0; c < CC; c++) s += q[qr][c] * k[kr][c];
        att[qr][kr] = s * rsqrtf((float)CC);
    }
    __syncthreads();
    if (t < 4) {
        float mx = att[t][0];
        for (int j = 1; j < 4; j++) mx = fmaxf(mx, att[t][j]);
        float e[4], sum = 0.f;
        for (int j = 0; j < 4; j++) { e[j] = __expf(att[t][j] - mx); sum += e[j]; }
        for (int j = 0; j < 4; j++) att[t][j] = e[j] / sum;
    }
    __syncthreads();
    for (int idx = t; idx < 4*CC; idx += 128) {
        int r = idx / CC, c = idx - r*CC;
        float s = 0.f;
        for (int kr = 0; kr < 4; kr++)
            s += att[r][kr] * g_qkv[(size_t)(g*4 + kr)*N3 + 2*CC + c];
        g_o[(size_t)(g*4 + r)*CC + c] = s;
    }
}

__global__ void __launch_bounds__(256) mean_kernel()
{
    if (g_flag == 0) return;
    for (int idx = blockIdx.x*blockDim.x + threadIdx.x; idx < BB*NCOARSE*CC;
         idx += gridDim.x*blockDim.x) {
        int g = idx / CC;
        int c = idx - g*CC;
        float s = 0.f;
        for (int r = 0; r < 4; r++) s += g_po[(size_t)(g*4 + r)*CC + c];
        g_mean[idx] = s * 0.25f;
    }
}

// ---------------- final ragged assembly (bias folded in) ----------------
__global__ void __launch_bounds__(256) assemble(
    const float* __restrict__ pos_fine, const float* __restrict__ pos_coarse,
    const float* __restrict__ cls_token, const float* __restrict__ mini_pos,
    const float* __restrict__ b_pe, float* __restrict__ out)
{
    int rid = blockIdx.x;
    int t = threadIdx.x;
    if (rid < FINE_ROWS) {
        int pos = g_finepos[rid];
        if (pos < 0) return;
        int f = rid % NFINE;
        const float* src = g_pe + (size_t)rid*CC;
        const float* pe  = pos_fine + (size_t)f*CC;
        float* dst = out + (size_t)pos*CC;
        for (int c = t; c < CC; c += 256) dst[c] = src[c] + b_pe[c] + pe[c];
    } else if (rid < FINE_ROWS + COARSE_ROWS) {
        int r = rid - FINE_ROWS;
        int pos = g_coarsepos[r];
        if (pos < 0) return;
        int cc = r % NCOARSE;
        const float* src = g_pe + (size_t)(FINE_ROWS + r)*CC;
        const float* pc  = pos_coarse + (size_t)cc*CC;
        const float* zz  = g_z + (size_t)r*CC;
        int flag = g_flag;
        float* dst = out + (size_t)pos*CC;
        for (int c = t; c < CC; c += 256)
            dst[c] = src[c] + b_pe[c] + pc[c] + (flag ? zz[c] : 0.0f);
    } else {
        int b = rid - FINE_ROWS - COARSE_ROWS;
        int pos = g_cls[b];
        float* dst = out + (size_t)pos*CC;
        for (int c = t; c < CC; c += 256) dst[c] = cls_token[c] + mini_pos[c];
    }
}

// ---------------- launch ----------------
template <typename T>
static void* sym_addr(const T& sym)
{
    void* p = nullptr;
    cudaGetSymbolAddress(&p, sym);
    return p;
}

extern "C" void kernel_launch(void* const* d_in, const int* in_sizes, int n_in,
                              void* d_out, int out_size)
{
    const float* x         = (const float*)d_in[0];
    const float* entropy   = (const float*)d_in[1];
    const float* W_pe      = (const float*)d_in[2];
    const float* b_pe      = (const float*)d_in[3];
    const float* qkv_w     = (const float*)d_in[4];
    const float* qkv_b     = (const float*)d_in[5];
    const float* proj_w    = (const float*)d_in[6];
    const float* proj_b    = (const float*)d_in[7];
    const float* mini_pos  = (const float*)d_in[8];
    const float* zero_w    = (const float*)d_in[9];
    const float* zero_b    = (const float*)d_in[10];
    const float* cls_token = (const float*)d_in[11];
    const float* pos_fine  = (const float*)d_in[12];
    const float* pos_coarse= (const float*)d_in[13];
    float* out = (float*)d_out;

    float* p_cpat    = (float*)sym_addr(g_cpat);
    float* p_pe      = (float*)sym_addr(g_pe);
    float* p_tok     = (float*)sym_addr(g_tok);
    float* p_qkv     = (float*)sym_addr(g_qkv);
    float* p_o       = (float*)sym_addr(g_o);
    float* p_po      = (float*)sym_addr(g_po);
    float* p_mean    = (float*)sym_addr(g_mean);
    float* p_z       = (float*)sym_addr(g_z);
    int*   p_flag    = (int*)  sym_addr(g_flag);

    // 1) flag scan (parallel) + masks/positions
    cudaMemsetAsync(p_flag, 0, sizeof(int));
    flag_scan<<<192, 256>>>(zero_w, zero_b);
    mask_kernel<<<1, 128>>>(entropy, out, out_size);

    // 2) coarse patch extraction (fine patches are gathered inside the GEMM)
    extract_coarse<<<(COARSE_ROWS*KDIM + 255)/256, 256>>>(x);

    // 3) combined patch-embed GEMM on tensor cores (TF32), A fused from x/cpat
    pe_gemm<<<dim3(CC/TBN, (ALL_ROWS + TBM-1)/TBM), 256>>>(x, p_cpat, W_pe, p_pe);

    // 4) mini-attention residual path — early-exits entirely when zero_w == 0
    const int MT = BB*NCOARSE*4;   // 12544
    build_tok<<<352, 256>>>(mini_pos, b_pe);
    sgemm_bias<<<dim3(N3/BN, (MT + BM-1)/BM), 256>>>(p_tok, qkv_w, qkv_b, p_qkv, MT, N3, CC, p_flag);
    mini_attn_kernel<<<BB*NCOARSE, 128>>>();
    sgemm_bias<<<dim3(CC/BN, (MT + BM-1)/BM), 256>>>(p_o, proj_w, proj_b, p_po, MT, CC, CC, p_flag);
    mean_kernel<<<352, 256>>>();
    sgemm_bias<<<dim3(CC/BN, (COARSE_ROWS + BM-1)/BM), 256>>>(p_mean, zero_w, zero_b, p_z,
                                                              COARSE_ROWS, CC, CC, p_flag);

    // 5) ragged assembly (cls + fine + coarse rows), b_pe folded in
    assemble<<<FINE_ROWS + COARSE_ROWS + BB, 256>>>(pos_fine, pos_coarse, cls_token,
                                                    mini_pos, b_pe, out);
}

// round 6
// speedup vs baseline: 1.9739x; 1.0541x over previous
#include <cuda_runtime.h>
#include <cuda_bf16.h>
#include <mma.h>
#include <cstdint>

using namespace nvcuda;

// ---------------- problem constants ----------------
#define BB   64
#define CC   768
#define NFINE 196
#define NCOARSE 49
#define KDIM 768
#define N3   2304
#define FINE_ROWS   (BB*NFINE)     // 12544
#define COARSE_ROWS (BB*NCOARSE)   // 3136
#define ALL_ROWS    (FINE_ROWS + COARSE_ROWS)  // 15680

// ---------------- device scratch (static, no allocs) ----------------
__device__ float g_cpat   [COARSE_ROWS*KDIM];
__device__ float g_pe     [ALL_ROWS*CC];       // only written when g_flag != 0
__device__ float g_tok    [BB*NCOARSE*4*CC];
__device__ float g_qkv    [BB*NCOARSE*4*N3];
__device__ float g_o      [BB*NCOARSE*4*CC];
__device__ float g_po     [BB*NCOARSE*4*CC];
__device__ float g_mean   [BB*NCOARSE*CC];
__device__ float g_z      [BB*NCOARSE*CC];
__device__ int   g_m32    [BB*NCOARSE];
__device__ int   g_finepos[BB*NFINE];
__device__ int   g_coarsepos[BB*NCOARSE];
__device__ int   g_seq[BB];
__device__ int   g_cls[BB];
__device__ int   g_total;
__device__ int   g_flag;

// ---------------- helpers ----------------
__device__ __forceinline__ uint32_t smem_u32(const void* p)
{
    uint32_t a;
    asm("{ .reg .u64 t; cvta.to.shared.u64 t, %1; cvt.u32.u64 %0, t; }" : "=r"(a) : "l"(p));
    return a;
}
__device__ __forceinline__ void cp_async16(uint32_t dst, const void* src, bool pred)
{
    int sz = pred ? 16 : 0;
    asm volatile("cp.async.cg.shared.global [%0], [%1], 16, %2;\n"
                 :: "r"(dst), "l"(src), "r"(sz));
}
__device__ __forceinline__ void cp_commit()  { asm volatile("cp.async.commit_group;\n"); }
__device__ __forceinline__ void cp_wait0()   { asm volatile("cp.async.wait_group 0;\n"); }

// ---------------- flag scan ----------------
__global__ void __launch_bounds__(256) flag_scan(
    const float* __restrict__ zw, const float* __restrict__ zb)
{
    int nz = 0;
    for (int i = blockIdx.x*blockDim.x + threadIdx.x; i < CC*CC; i += gridDim.x*blockDim.x)
        nz |= (zw[i] != 0.0f);
    if (blockIdx.x == 0)
        for (int i = threadIdx.x; i < CC; i += blockDim.x) nz |= (zb[i] != 0.0f);
    if (__syncthreads_or(nz) && threadIdx.x == 0) atomicOr(&g_flag, 1);
}

// ---------------- mask / positions ----------------
__global__ void __launch_bounds__(128) mask_kernel(
    const float* __restrict__ e, float* __restrict__ out, int out_size)
{
    __shared__ int s_nc[BB];
    __shared__ int s_cls[BB+1];
    int t = threadIdx.x;
    if (t < BB) {
        int b = t, nc = 0;
        const float* eb = e + b*NFINE;
        for (int cc = 0; cc < NCOARSE; cc++) {
            int ci = cc / 7, cj = cc % 7;
            float m = (eb[(2*ci)*14 + 2*cj]   + eb[(2*ci)*14 + 2*cj+1] +
                       eb[(2*ci+1)*14 + 2*cj] + eb[(2*ci+1)*14 + 2*cj+1]) * 0.25f;
            int sel = m < 0.5f;
            g_m32[b*NCOARSE + cc] = sel;
            nc += sel;
        }
        s_nc[t] = nc;
    }
    __syncthreads();
    if (t == 0) {
        int acc = 0;
        for (int b = 0; b < BB; b++) {
            s_cls[b] = acc;
            g_cls[b] = acc;
            int nc = s_nc[b];
            int seq = 1 + 4*(NCOARSE - nc) + nc;
            g_seq[b] = seq;
            acc += seq;
        }
        g_total = acc;
        s_cls[BB] = acc;
    }
    __syncthreads();
    if (t < BB) {
        int b = t;
        int base = s_cls[b];
        int rank = 0;
        for (int f = 0; f < NFINE; f++) {
            int i = f / 14, j = f % 14;
            int sel = g_m32[b*NCOARSE + (i>>1)*7 + (j>>1)];
            g_finepos[b*NFINE + f] = sel ? -1 : (base + 1 + rank);
            rank += !sel;
        }
        int crank = 0;
        for (int cc = 0; cc < NCOARSE; cc++) {
            int sel = g_m32[b*NCOARSE + cc];
            g_coarsepos[b*NCOARSE + cc] = sel ? (base + 1 + rank + crank) : -1;
            crank += sel;
        }
    }
    __syncthreads();
    long long total = s_cls[BB];
    long long need = total * CC + 2*BB;
    if ((long long)out_size == need && t < BB) {
        out[total*CC + t]      = (float)g_seq[t];
        out[total*CC + BB + t] = (float)g_cls[t];
    }
}

// ---------------- cls rows (always) ----------------
__global__ void __launch_bounds__(256) cls_kernel(
    const float* __restrict__ cls_token, const float* __restrict__ mini_pos,
    float* __restrict__ out)
{
    int b = blockIdx.x;
    int pos = g_cls[b];
    float* dst = out + (size_t)pos*CC;
    for (int c = threadIdx.x; c < CC; c += 256) dst[c] = cls_token[c] + mini_pos[c];
}

// ---------------- coarse patch extraction ----------------
__global__ void __launch_bounds__(256) extract_coarse(const float* __restrict__ x)
{
    int idx = blockIdx.x * blockDim.x + threadIdx.x;
    if (idx >= COARSE_ROWS*KDIM) return;
    int row = idx / KDIM;
    int k   = idx - row * KDIM;
    int c  = k >> 8;
    int pi = (k >> 4) & 15;
    int pj = k & 15;
    int b  = row / NCOARSE;
    int cc = row - b * NCOARSE;
    int ci = cc / 7, cj = cc - ci*7;
    int y = (ci*16 + pi) * 2;
    int xx = (cj*16 + pj) * 2;
    const float* base = x + ((size_t)(b*3 + c)*224 + y)*224 + xx;
    g_cpat[idx] = (base[0] + base[1] + base[224] + base[225]) * 0.25f;
}

// ---------------- TF32 tensor-core GEMM, fused epilogue ----------------
// pe = Apatch @ W_pe; A gathered from x (fine) / g_cpat (coarse).
// When g_flag==0 the epilogue scatters straight to out (+b_pe +pos embeds);
// when g_flag!=0 it writes g_pe and the guarded assemble finishes the job.
#define TBM 128
#define TBN 128
#define TBK 32
#define AS_STRIDE (TBK + 4)       // 36
#define BS_STRIDE (TBN + 4)       // 132
#define AS_FLOATS (2*TBM*AS_STRIDE)          // 9216
#define BS_FLOATS (2*TBK*BS_STRIDE)          // 8448
#define CS_STRIDE 132
#define SMEM_BYTES ((AS_FLOATS + BS_FLOATS) * 4)   // 70656

__global__ void __launch_bounds__(256, 2) pe_gemm(
    const float* __restrict__ x, const float* __restrict__ cpat,
    const float* __restrict__ Bm,
    const float* __restrict__ b_pe, const float* __restrict__ pos_fine,
    const float* __restrict__ pos_coarse, float* __restrict__ out,
    float* __restrict__ pe)
{
    extern __shared__ float sm[];
    float* As = sm;                   // [2][TBM][AS_STRIDE]
    float* Bs = sm + AS_FLOATS;       // [2][TBK][BS_STRIDE]

    const int M = ALL_ROWS, N = CC, K = KDIM;
    int tid  = threadIdx.x;
    int warp = tid >> 5;
    int wr   = warp >> 1;     // 0..3
    int wc   = warp & 1;      // 0..1
    int row0 = blockIdx.y * TBM;
    int col0 = blockIdx.x * TBN;

    // A-load coords: 4 float4 per thread per stage
    int ar[4], ac4[4];
    int afine[4], ab[4], ai[4], aj[4];
    const float* abase[4];
#pragma unroll
    for (int it = 0; it < 4; it++) {
        int lin = tid + it*256;          // 0..1023
        int r   = lin >> 3;              // 0..127
        int c4  = (lin & 7) << 2;        // 0..28
        ar[it] = r; ac4[it] = c4;
        int gm = row0 + r;
        int gmc = gm < M ? gm : M-1;
        afine[it] = (gmc < FINE_ROWS);
        if (afine[it]) {
            int b = gmc / NFINE;
            int f = gmc - b*NFINE;
            ab[it] = b; ai[it] = f / 14; aj[it] = f - (f/14)*14;
        } else {
            abase[it] = cpat + (size_t)(gmc - FINE_ROWS)*KDIM;
        }
    }
    // B-load coords: 4 float4 per thread per stage
    int br[4], bc4[4];
#pragma unroll
    for (int it = 0; it < 4; it++) {
        int lin = tid + it*256;
        br[it]  = lin >> 5;              // 0..31
        bc4[it] = (lin & 31) << 2;       // 0..124
    }

    wmma::fragment<wmma::accumulator, 16, 16, 8, float> acc[2][4];
#pragma unroll
    for (int i = 0; i < 2; i++)
#pragma unroll
        for (int j = 0; j < 4; j++) wmma::fill_fragment(acc[i][j], 0.0f);

    auto load_stage = [&](int buf, int k0) {
        float* Ab = As + buf*TBM*AS_STRIDE;
        float* Bb = Bs + buf*TBK*BS_STRIDE;
#pragma unroll
        for (int it = 0; it < 4; it++) {
            int gm = row0 + ar[it];
            bool pred = gm < M;
            const float* src;
            if (afine[it]) {
                int kc = k0 + ac4[it];
                int c  = kc >> 8;
                int pi = (kc >> 4) & 15;
                int pj = kc & 15;
                src = x + ((size_t)(ab[it]*3 + c)*224 + ai[it]*16 + pi)*224 + aj[it]*16 + pj;
            } else {
                src = abase[it] + k0 + ac4[it];
            }
            cp_async16(smem_u32(&Ab[ar[it]*AS_STRIDE + ac4[it]]), src, pred);
        }
#pragma unroll
        for (int it = 0; it < 4; it++) {
            const float* src = Bm + (size_t)(k0 + br[it])*N + col0 + bc4[it];
            cp_async16(smem_u32(&Bb[br[it]*BS_STRIDE + bc4[it]]), src, true);
        }
        cp_commit();
    };

    load_stage(0, 0);
    const int nK = K / TBK;   // 24
    for (int kt = 0; kt < nK; kt++) {
        int cur = kt & 1;
        cp_wait0();
        __syncthreads();
        if (kt + 1 < nK) load_stage(cur ^ 1, (kt+1)*TBK);

        float* Ab = As + cur*TBM*AS_STRIDE;
        float* Bb = Bs + cur*TBK*BS_STRIDE;
#pragma unroll
        for (int kk = 0; kk < TBK; kk += 8) {
            wmma::fragment<wmma::matrix_a, 16, 16, 8, wmma::precision::tf32, wmma::row_major> af[2];
            wmma::fragment<wmma::matrix_b, 16, 16, 8, wmma::precision::tf32, wmma::row_major> bf[4];
            // NOTE: no __float_to_tf32 — hardware reads the tf32 bit-slice of f32
#pragma unroll
            for (int i = 0; i < 2; i++)
                wmma::load_matrix_sync(af[i], &Ab[(wr*32 + i*16)*AS_STRIDE + kk], AS_STRIDE);
#pragma unroll
            for (int j = 0; j < 4; j++)
                wmma::load_matrix_sync(bf[j], &Bb[kk*BS_STRIDE + wc*64 + j*16], BS_STRIDE);
#pragma unroll
            for (int i = 0; i < 2; i++)
#pragma unroll
                for (int j = 0; j < 4; j++)
                    wmma::mma_sync(acc[i][j], af[i], bf[j], acc[i][j]);
        }
        __syncthreads();
    }

    // ---- fused epilogue: stage tile in smem, then scatter ----
    float* Cs = sm;    // [TBM][CS_STRIDE], 67584 B <= SMEM_BYTES
#pragma unroll
    for (int i = 0; i < 2; i++)
#pragma unroll
        for (int j = 0; j < 4; j++)
            wmma::store_matrix_sync(&Cs[(wr*32 + i*16)*CS_STRIDE + wc*64 + j*16],
                                    acc[i][j], CS_STRIDE, wmma::mem_row_major);
    __syncthreads();

    int r    = tid >> 1;            // 0..127
    int half = tid & 1;             // 0..1
    int gm = row0 + r;
    if (gm >= M) return;
    int cbase = half*64;
    const float* srow = &Cs[r*CS_STRIDE + cbase];
    int flag = g_flag;

    if (flag) {
        float* dst = pe + (size_t)gm*CC + col0 + cbase;
#pragma unroll
        for (int q = 0; q < 16; q++)
            *reinterpret_cast<float4*>(dst + q*4) =
                *reinterpret_cast<const float4*>(srow + q*4);
        return;
    }

    int pos, erow;
    const float* etab;
    if (gm < FINE_ROWS) {
        pos  = g_finepos[gm];
        erow = gm % NFINE;
        etab = pos_fine;
    } else {
        int rr = gm - FINE_ROWS;
        pos  = g_coarsepos[rr];
        erow = rr % NCOARSE;
        etab = pos_coarse;
    }
    if (pos < 0) return;
    const float* bp = b_pe + col0 + cbase;
    const float* ep = etab + (size_t)erow*CC + col0 + cbase;
    float* dst = out + (size_t)pos*CC + col0 + cbase;
#pragma unroll
    for (int q = 0; q < 16; q++) {
        float4 v = *reinterpret_cast<const float4*>(srow + q*4);
        float4 b = *reinterpret_cast<const float4*>(bp + q*4);
        float4 e = *reinterpret_cast<const float4*>(ep + q*4);
        *reinterpret_cast<float4*>(dst + q*4) =
            make_float4(v.x + b.x + e.x, v.y + b.y + e.y,
                        v.z + b.z + e.z, v.w + b.w + e.w);
    }
}

// ---------------- fp32 SGEMM (flag-guarded mini-attn path only) ----------------
#define BM 128
#define BN 128
#define BK 8
__global__ void __launch_bounds__(256) sgemm_bias(
    const float* __restrict__ A, const float* __restrict__ Bm,
    const float* __restrict__ bias, float* __restrict__ Cm,
    int M, int N, int K, const int* flagptr)
{
    if (flagptr && *flagptr == 0) return;
    __shared__ float As[BK][BM];
    __shared__ float Bs[BK][BN];
    int tid = threadIdx.x;
    int row0 = blockIdx.y * BM;
    int col0 = blockIdx.x * BN;
    int tx = tid & 15;
    int ty = tid >> 4;
    float acc[8][8];
#pragma unroll
    for (int i = 0; i < 8; i++)
#pragma unroll
        for (int j = 0; j < 8; j++) acc[i][j] = 0.0f;

    int aRow = tid >> 1;
    int aCol = (tid & 1) * 4;
    int bRow = tid >> 5;
    int bCol = (tid & 31) * 4;

    for (int k0 = 0; k0 < K; k0 += BK) {
        float4 av = make_float4(0.f, 0.f, 0.f, 0.f);
        int gm = row0 + aRow;
        if (gm < M) av = *reinterpret_cast<const float4*>(&A[(size_t)gm*K + k0 + aCol]);
        As[aCol+0][aRow] = av.x;
        As[aCol+1][aRow] = av.y;
        As[aCol+2][aRow] = av.z;
        As[aCol+3][aRow] = av.w;
        float4 bv = *reinterpret_cast<const float4*>(&Bm[(size_t)(k0 + bRow)*N + col0 + bCol]);
        *reinterpret_cast<float4*>(&Bs[bRow][bCol]) = bv;
        __syncthreads();
#pragma unroll
        for (int kk = 0; kk < BK; kk++) {
            float4 a0 = *reinterpret_cast<const float4*>(&As[kk][ty*8]);
            float4 a1 = *reinterpret_cast<const float4*>(&As[kk][ty*8+4]);
            float4 b0 = *reinterpret_cast<const float4*>(&Bs[kk][tx*8]);
            float4 b1 = *reinterpret_cast<const float4*>(&Bs[kk][tx*8+4]);
            float a[8] = {a0.x,a0.y,a0.z,a0.w,a1.x,a1.y,a1.z,a1.w};
            float b[8] = {b0.x,b0.y,b0.z,b0.w,b1.x,b1.y,b1.z,b1.w};
#pragma unroll
            for (int i = 0; i < 8; i++)
#pragma unroll
                for (int j = 0; j < 8; j++) acc[i][j] += a[i] * b[j];
        }
        __syncthreads();
    }
    float4 bi0 = *reinterpret_cast<const float4*>(&bias[col0 + tx*8]);
    float4 bi1 = *reinterpret_cast<const float4*>(&bias[col0 + tx*8 + 4]);
#pragma unroll
    for (int i = 0; i < 8; i++) {
        int gm = row0 + ty*8 + i;
        if (gm < M) {
            float* cp = Cm + (size_t)gm*N + col0 + tx*8;
            float4 r0 = make_float4(acc[i][0]+bi0.x, acc[i][1]+bi0.y, acc[i][2]+bi0.z, acc[i][3]+bi0.w);
            float4 r1 = make_float4(acc[i][4]+bi1.x, acc[i][5]+bi1.y, acc[i][6]+bi1.z, acc[i][7]+bi1.w);
            *reinterpret_cast<float4*>(cp)     = r0;
            *reinterpret_cast<float4*>(cp + 4) = r1;
        }
    }
}

// ---------------- mini-attention path (flag-guarded; dead when zero_w==0) ----------------
__global__ void __launch_bounds__(256) build_tok(const float* __restrict__ mini_pos,
                                                 const float* __restrict__ b_pe)
{
    if (g_flag == 0) return;
    for (int idx = blockIdx.x*blockDim.x + threadIdx.x; idx < BB*NCOARSE*4*CC;
         idx += gridDim.x*blockDim.x) {
        int c = idx % CC;
        int r = (idx / CC) & 3;
        int g = idx / (4*CC);
        int b = g / NCOARSE;
        int cc = g - b*NCOARSE;
        int ci = cc / 7, cj = cc - ci*7;
        int di = r >> 1, dj = r & 1;
        int f = (2*ci + di)*14 + (2*cj + dj);
        g_tok[idx] = g_pe[(size_t)(b*NFINE + f)*CC + c] + b_pe[c] + mini_pos[r*CC + c];
    }
}

__global__ void __launch_bounds__(128) mini_attn_kernel()
{
    if (g_flag == 0) return;
    int g = blockIdx.x;
    if (!g_m32[g]) return;
    __shared__ float q[4][CC];
    __shared__ float k[4][CC];
    __shared__ float att[4][4];
    int t = threadIdx.x;
    for (int idx = t; idx < 4*CC; idx += 128) {
        int r = idx / CC, c = idx - r*CC;
        q[r][c] = g_qkv[(size_t)(g*4 + r)*N3 + c];
        k[r][c] = g_qkv[(size_t)(g*4 + r)*N3 + CC + c];
    }
    __syncthreads();
    if (t < 16) {
        int qr = t >> 2, kr = t & 3;
        float s = 0.f;
        for (int c = 0; c < CC; c++) s += q[qr][c] * k[kr][c];
        att[qr][kr] = s * rsqrtf((float)CC);
    }
    __syncthreads();
    if (t < 4) {
        float mx = att[t][0];
        for (int j = 1; j < 4; j++) mx = fmaxf(mx, att[t][j]);
        float e[4], sum = 0.f;
        for (int j = 0; j < 4; j++) { e[j] = __expf(att[t][j] - mx); sum += e[j]; }
        for (int j = 0; j < 4; j++) att[t][j] = e[j] / sum;
    }
    __syncthreads();
    for (int idx = t; idx < 4*CC; idx += 128) {
        int r = idx / CC, c = idx - r*CC;
        float s = 0.f;
        for (int kr = 0; kr < 4; kr++)
            s += att[r][kr] * g_qkv[(size_t)(g*4 + kr)*N3 + 2*CC + c];
        g_o[(size_t)(g*4 + r)*CC + c] = s;
    }
}

__global__ void __launch_bounds__(256) mean_kernel()
{
    if (g_flag == 0) return;
    for (int idx = blockIdx.x*blockDim.x + threadIdx.x; idx < BB*NCOARSE*CC;
         idx += gridDim.x*blockDim.x) {
        int g = idx / CC;
        int c = idx - g*CC;
        float s = 0.f;
        for (int r = 0; r < 4; r++) s += g_po[(size_t)(g*4 + r)*CC + c];
        g_mean[idx] = s * 0.25f;
    }
}

// ---------------- assemble (only used when g_flag != 0) ----------------
__global__ void __launch_bounds__(256) assemble(
    const float* __restrict__ pos_fine, const float* __restrict__ pos_coarse,
    const float* __restrict__ b_pe, float* __restrict__ out)
{
    if (g_flag == 0) return;
    int rid = blockIdx.x;
    int t = threadIdx.x;
    if (rid < FINE_ROWS) {
        int pos = g_finepos[rid];
        if (pos < 0) return;
        int f = rid % NFINE;
        const float* src = g_pe + (size_t)rid*CC;
        const float* pe  = pos_fine + (size_t)f*CC;
        float* dst = out + (size_t)pos*CC;
        for (int c = t; c < CC; c += 256) dst[c] = src[c] + b_pe[c] + pe[c];
    } else {
        int r = rid - FINE_ROWS;
        int pos = g_coarsepos[r];
        if (pos < 0) return;
        int cc = r % NCOARSE;
        const float* src = g_pe + (size_t)(FINE_ROWS + r)*CC;
        const float* pc  = pos_coarse + (size_t)cc*CC;
        const float* zz  = g_z + (size_t)r*CC;
        float* dst = out + (size_t)pos*CC;
        for (int c = t; c < CC; c += 256)
            dst[c] = src[c] + b_pe[c] + pc[c] + zz[c];
    }
}

// ---------------- launch ----------------
template <typename T>
static void* sym_addr(const T& sym)
{
    void* p = nullptr;
    cudaGetSymbolAddress(&p, sym);
    return p;
}

extern "C" void kernel_launch(void* const* d_in, const int* in_sizes, int n_in,
                              void* d_out, int out_size)
{
    const float* x         = (const float*)d_in[0];
    const float* entropy   = (const float*)d_in[1];
    const float* W_pe      = (const float*)d_in[2];
    const float* b_pe      = (const float*)d_in[3];
    const float* qkv_w     = (const float*)d_in[4];
    const float* qkv_b     = (const float*)d_in[5];
    const float* proj_w    = (const float*)d_in[6];
    const float* proj_b    = (const float*)d_in[7];
    const float* mini_pos  = (const float*)d_in[8];
    const float* zero_w    = (const float*)d_in[9];
    const float* zero_b    = (const float*)d_in[10];
    const float* cls_token = (const float*)d_in[11];
    const float* pos_fine  = (const float*)d_in[12];
    const float* pos_coarse= (const float*)d_in[13];
    float* out = (float*)d_out;

    float* p_cpat    = (float*)sym_addr(g_cpat);
    float* p_pe      = (float*)sym_addr(g_pe);
    float* p_tok     = (float*)sym_addr(g_tok);
    float* p_qkv     = (float*)sym_addr(g_qkv);
    float* p_o       = (float*)sym_addr(g_o);
    float* p_po      = (float*)sym_addr(g_po);
    float* p_mean    = (float*)sym_addr(g_mean);
    float* p_z       = (float*)sym_addr(g_z);
    int*   p_flag    = (int*)  sym_addr(g_flag);

    static bool attr_done = false;
    if (!attr_done) {
        cudaFuncSetAttribute(pe_gemm, cudaFuncAttributeMaxDynamicSharedMemorySize, SMEM_BYTES);
        attr_done = true;
    }

    // 1) flag scan + masks/positions + coarse extraction
    cudaMemsetAsync(p_flag, 0, sizeof(int));
    flag_scan<<<192, 256>>>(zero_w, zero_b);
    mask_kernel<<<1, 128>>>(entropy, out, out_size);
    extract_coarse<<<(COARSE_ROWS*KDIM + 255)/256, 256>>>(x);
    cls_kernel<<<BB, 256>>>(cls_token, mini_pos, out);

    // 2) fused patch-embed GEMM (TF32 wmma, truncated inputs, scatter epilogue)
    pe_gemm<<<dim3(CC/TBN, (ALL_ROWS + TBM-1)/TBM), 256, SMEM_BYTES>>>(
        x, p_cpat, W_pe, b_pe, pos_fine, pos_coarse, out, p_pe);

    // 3) mini-attention residual path — dead when zero_w == 0
    const int MT = BB*NCOARSE*4;   // 12544
    build_tok<<<352, 256>>>(mini_pos, b_pe);
    sgemm_bias<<<dim3(N3/BN, (MT + BM-1)/BM), 256>>>(p_tok, qkv_w, qkv_b, p_qkv, MT, N3, CC, p_flag);
    mini_attn_kernel<<<BB*NCOARSE, 128>>>();
    sgemm_bias<<<dim3(CC/BN, (MT + BM-1)/BM), 256>>>(p_o, proj_w, proj_b, p_po, MT, CC, CC, p_flag);
    mean_kernel<<<352, 256>>>();
    sgemm_bias<<<dim3(CC/BN, (COARSE_ROWS + BM-1)/BM), 256>>>(p_mean, zero_w, zero_b, p_z,
                                                              COARSE_ROWS, CC, CC, p_flag);

    // 4) assemble (no-op unless zero_w/zero_b nonzero)
    assemble<<<FINE_ROWS + COARSE_ROWS, 256>>>(pos_fine, pos_coarse, b_pe, out);
}